// round 17
// baseline (speedup 1.0000x reference)
#include <cuda_runtime.h>
#include <math.h>

#define NN   20000
#define E1C  100000
#define E2C  100000
#define HN   (NN*128)
#define NEF  220000
#define CUTV 6.0f
#define PI_F 3.14159265358979f
#define FSL  68    /* feats fp32 stride: 68%32=4 -> conflict-light */
#define VGL  132   /* rg buffer stride */

#define NB0  3125
#define NB1  625
#define NB2  3125
#define NBT  (NB0+NB1+NB2)

typedef unsigned long long u64t;

/* ---------------- persistent device scratch ---------------- */
__device__ __align__(16) float g_WcT[256*128];
__device__ __align__(16) float g_Wc2dT[64*128];
__device__ __align__(16) float g_WcrbfT[64*128];
__device__ __align__(16) float g_etb[3*128];
__device__ __align__(16) float g_cvec[128];
__device__ __align__(16) float g_nproj[(size_t)2*NN*128];
/* pre-swizzled bf16 B fragments: [qc(3)][kt(12)][ntile(16)][lane(32)] x uint4 */
__device__ __align__(16) uint4 g_WfHL[576*32];
/* v_gate scratch: one 128-vector per edge (written qc1, read in V pass) */
__device__ __align__(16) float g_vg[(size_t)NEF*128];
__device__ unsigned char g_mask[NN];   /* zero at load; only 1s written (idempotent) */

/* -------- packed f32x2 helpers -------- */
__device__ __forceinline__ u64t fma2d(u64t a, u64t b, u64t c) {
    u64t d; asm("fma.rn.f32x2 %0, %1, %2, %3;" : "=l"(d) : "l"(a), "l"(b), "l"(c));
    return d;
}
__device__ __forceinline__ u64t splat2(float x) {
    u64t d; asm("mov.b64 %0, {%1, %1};" : "=l"(d) : "r"(__float_as_uint(x)));
    return d;
}
__device__ __forceinline__ u64t fadd2(u64t a, u64t b) { return fma2d(a, splat2(1.0f), b); }
__device__ __forceinline__ float lo2(u64t d) { return __uint_as_float((unsigned)(d & 0xffffffffull)); }
__device__ __forceinline__ float hi2(u64t d) { return __uint_as_float((unsigned)(d >> 32)); }
__device__ __forceinline__ void red2(float* p, float a, float b) {
    asm volatile("red.global.add.v2.f32 [%0], {%1, %2};" :: "l"(p), "f"(a), "f"(b) : "memory");
}
__device__ __forceinline__ void red4(float* p, float a, float b, float c, float d) {
    asm volatile("red.global.add.v4.f32 [%0], {%1, %2, %3, %4};"
                 :: "l"(p), "f"(a), "f"(b), "f"(c), "f"(d) : "memory");
}
__device__ __forceinline__ void bfsplit2(float x, float y, unsigned& hi, unsigned& lo) {
    unsigned h; asm("cvt.rn.bf16x2.f32 %0, %1, %2;" : "=r"(h) : "f"(y), "f"(x));
    float xh = __uint_as_float(h << 16);
    float yh = __uint_as_float(h & 0xffff0000u);
    asm("cvt.rn.bf16x2.f32 %0, %1, %2;" : "=r"(lo) : "f"(y - yh), "f"(x - xh));
    hi = h;
}
__device__ __forceinline__ void ldmA(unsigned a[4], unsigned saddr) {
    asm volatile("ldmatrix.sync.aligned.m8n8.x4.shared.b16 {%0,%1,%2,%3}, [%4];"
                 : "=r"(a[0]), "=r"(a[1]), "=r"(a[2]), "=r"(a[3]) : "r"(saddr));
}
__device__ __forceinline__ void mmabf(float* d, const unsigned a[4], unsigned bx, unsigned by) {
    asm volatile("mma.sync.aligned.m16n8k16.row.col.f32.bf16.bf16.f32 "
                 "{%0,%1,%2,%3}, {%4,%5,%6,%7}, {%8,%9}, {%0,%1,%2,%3};"
                 : "+f"(d[0]), "+f"(d[1]), "+f"(d[2]), "+f"(d[3])
                 : "r"(a[0]), "r"(a[1]), "r"(a[2]), "r"(a[3]), "r"(bx), "r"(by));
}

/* ---------------- fused precompute + maskset ---------------- */
__global__ void k_pre(const float* __restrict__ W_i, const float* __restrict__ W_phi1,
                      const float* __restrict__ b_phi1, const float* __restrict__ W_e2d,
                      const float* __restrict__ W_rbf, const float* __restrict__ ET,
                      const float* __restrict__ virt,
                      const float* __restrict__ W_phi2, const float* __restrict__ W_msg,
                      const int* __restrict__ Edist_idx)
{
    int b = blockIdx.x;
    int t = threadIdx.x;
    if (b < 194) {
        int idx = b*256 + t;
        if (idx < 32768) {
            int k = idx >> 7, p = idx & 127;
            float s = 0.f;
            #pragma unroll 4
            for (int j = 0; j < 128; j++) s += W_phi1[p*288 + j] * W_i[j*256 + k];
            g_WcT[idx] = s;
        } else if (idx < 40960) {
            int i = idx - 32768; int k = i >> 7, p = i & 127;
            float s = 0.f;
            #pragma unroll 4
            for (int j = 0; j < 128; j++) s += W_phi1[p*288 + 128 + j] * W_e2d[j*64 + k];
            g_Wc2dT[i] = s;
        } else if (idx < 49152) {
            int i = idx - 40960; int k = i >> 7, p = i & 127;
            float s = 0.f;
            #pragma unroll 4
            for (int j = 0; j < 128; j++) s += W_phi1[p*288 + 128 + j] * W_rbf[j*64 + k];
            g_WcrbfT[i] = s;
        } else if (idx < 49536) {
            int i = idx - 49152; int tt = i >> 7, p = i & 127;
            float s = b_phi1[p];
            #pragma unroll
            for (int l = 0; l < 32; l++) s += W_phi1[p*288 + 256 + l] * ET[tt*32 + l];
            g_etb[i] = s;
        }
    } else if (b == 194) {
        __shared__ float u[128];
        if (t < 128) {
            float s = 0.f;
            #pragma unroll 4
            for (int j = 0; j < 128; j++) s += W_i[t*256 + 128 + j] * virt[j];
            u[t] = s;
        }
        __syncthreads();
        if (t < 128) {
            float c = 0.f;
            #pragma unroll 4
            for (int q = 0; q < 128; q++) c += W_phi1[t*288 + q] * u[q];
            g_cvec[t] = c;
        }
    } else if (b < 339) {
        /* B fragment build */
        int idx = (b - 195)*256 + t;
        if (idx < 36864) {
            int rec  = idx >> 6;
            int wi   = idx & 63;
            int lane = wi >> 1;
            int half = wi & 1;
            int nt = rec & 15;
            int kt = (rec >> 4) % 12;
            int qc = rec / 192;
            int ch = qc*128 + nt*8 + (lane >> 2);
            int k0 = kt*16 + (lane & 3)*2 + half*8;
            float w0, w1;
            if (k0 < 128) {
                w0 = W_phi2[(size_t)ch*128 + k0];
                w1 = W_phi2[(size_t)ch*128 + k0 + 1];
            } else {
                w0 = W_msg[(size_t)ch*64 + k0 - 128];
                w1 = W_msg[(size_t)ch*64 + k0 - 127];
            }
            unsigned hi, lo;
            bfsplit2(w0, w1, hi, lo);
            ((unsigned*)g_WfHL)[rec*128 + lane*4 + half]     = hi;
            ((unsigned*)g_WfHL)[rec*128 + lane*4 + 2 + half] = lo;
        }
    } else {
        int idx = (b - 339)*256 + t;
        if (idx < 2*E2C) g_mask[Edist_idx[idx]] = 1;
    }
}

/* ---------------- node projection (packed f32x2) ---------------- */
__global__ void __launch_bounds__(128) k_nproj(const float* __restrict__ H,
                                               const float* __restrict__ H2d)
{
    __shared__ float hx[16*128];
    __shared__ float h2[16*128];
    int t = threadIdx.x;
    int i0 = blockIdx.x * 16;
    #pragma unroll
    for (int it = 0; it < 16; it++) {
        int idx = t + it*128;
        int nd = idx >> 7, p = idx & 127;
        hx[idx] = H  [(size_t)(i0+nd)*128 + p];
        h2[idx] = H2d[(size_t)(i0+nd)*128 + p];
    }
    __syncthreads();
    int tn = t >> 6;
    int tp = t & 63;
    int p0 = tp * 2;
    const float* hxp = hx + tn*8*128;
    const float* h2p = h2 + tn*8*128;
    u64t a1[8], a2[8];
    #pragma unroll
    for (int nd = 0; nd < 8; nd++) { a1[nd] = 0; a2[nd] = 0; }
    #pragma unroll 2
    for (int k4 = 0; k4 < 128; k4 += 4) {
        float4 xv[8], yv[8];
        #pragma unroll
        for (int nd = 0; nd < 8; nd++) {
            xv[nd] = *(const float4*)(hxp + nd*128 + k4);
            yv[nd] = *(const float4*)(h2p + nd*128 + k4);
        }
        #pragma unroll
        for (int kk = 0; kk < 4; kk++) {
            u64t w1 = *(const u64t*)&g_WcT[(size_t)(k4+kk)*128 + p0];
            u64t w2 = *(const u64t*)&g_WcT[(size_t)(128+k4+kk)*128 + p0];
            #pragma unroll
            for (int nd = 0; nd < 8; nd++) {
                a1[nd] = fma2d(splat2(((const float*)&xv[nd])[kk]), w1, a1[nd]);
                a2[nd] = fma2d(splat2(((const float*)&yv[nd])[kk]), w2, a2[nd]);
            }
        }
    }
    u64t cv2 = *(const u64t*)&g_cvec[p0];
    #pragma unroll
    for (int nd = 0; nd < 8; nd++) {
        int node = i0 + tn*8 + nd;
        *(u64t*)&g_nproj[(size_t)node*128 + p0]      = fadd2(a1[nd], a2[nd]);
        *(u64t*)&g_nproj[(size_t)(NN+node)*128 + p0] = fadd2(a1[nd], cv2);
    }
}

/* ------- fp32 GEMM micro-kernel (phase A only), feats stride FSL ------- */
__device__ __forceinline__ void gemm64s(const float* __restrict__ W,
                                        const float* __restrict__ xsp,
                                        int c0, int c1, u64t (&acc)[4][4])
{
    #pragma unroll 2
    for (int k4 = 0; k4 < 64; k4 += 4) {
        float4 xv[4];
        #pragma unroll
        for (int j = 0; j < 4; j++)
            xv[j] = *(const float4*)(xsp + j*(4*FSL) + k4);
        #pragma unroll
        for (int kk = 0; kk < 4; kk++) {
            ulonglong2 wA = *(const ulonglong2*)(W + (size_t)(k4+kk)*128 + c0);
            ulonglong2 wB = *(const ulonglong2*)(W + (size_t)(k4+kk)*128 + c1);
            #pragma unroll
            for (int j = 0; j < 4; j++) {
                u64t a = splat2(((const float*)&xv[j])[kk]);
                acc[0][j] = fma2d(a, wA.x, acc[0][j]);
                acc[1][j] = fma2d(a, wA.y, acc[1][j]);
                acc[2][j] = fma2d(a, wB.x, acc[2][j]);
                acc[3][j] = fma2d(a, wB.y, acc[3][j]);
            }
        }
    }
}

/* ---------------- fused per-edge kernel: 32 edges / 128 threads ---------------- */
__global__ void __launch_bounds__(128, 4) k_edge(
    const int* __restrict__ E2d_idx, const float* __restrict__ E2d_feat,
    const int* __restrict__ Edist_idx, const float* __restrict__ Edist_val,
    const float* __restrict__ Z, const float* __restrict__ Z3d,
    const float* __restrict__ V,
    const float* __restrict__ b_phi2, const float* __restrict__ b_msg,
    float* __restrict__ out)
{
    extern __shared__ float sm[];
    float*    feats = sm;                             /* 32 x 68 fp32 (phase A input) */
    unsigned* xshiw = (unsigned*)(sm + 32*FSL);       /* 32 x 100 u32 (bf16x2 hi) */
    unsigned* xslow = xshiw + 3200;                   /* 32 x 100 u32 (bf16x2 lo) */
    float*    rgbuf = (float*)xshiw;                  /* alias post-qc2: 4224 <= 6400 */
    int*   srow  = (int*)(xslow + 3200);
    int*   scol  = srow + 32;
    float* sdist = (float*)(scol + 32);
    float* senvd = sdist + 32;
    float* sdval = senvd + 32;
    float* senv2 = sdval + 32;
    float* sunit = senv2 + 32;                        /* 32 x 3 */

    int t  = threadIdx.x;
    int w  = t >> 5;
    int l  = t & 31;
    int tp = l & 7;
    int te = l >> 3;
    int cb = (w & 1) * 64;
    int eb = (w >> 1) * 16;
    int c0 = cb + tp*4;
    int c1 = cb + 32 + tp*4;
    int ebte = eb + te;

    int bid = blockIdx.x;
    int base = bid * 32;
    int type = (bid < NB0) ? 0 : (bid < NB0+NB1 ? 1 : 2);

    /* --- metadata + geometry (warp 0) --- */
    if (t < 32) {
        int eg = base + t;
        int row, col; float dval = 0.f;
        if (type == 0)      { row = E2d_idx[eg]; col = E2d_idx[E1C + eg]; }
        else if (type == 1) { int i = eg - E1C; row = i; col = NN + i; }
        else                { int j = eg - E1C - NN; row = Edist_idx[j];
                              col = Edist_idx[E2C + j]; dval = Edist_val[j]; }
        srow[t] = row; scol[t] = col; sdval[t] = dval;
        float zr0 = Z[row*3+0], zr1 = Z[row*3+1], zr2 = Z[row*3+2];
        float zc0, zc1, zc2;
        if (col < NN) { zc0 = Z[col*3+0]; zc1 = Z[col*3+1]; zc2 = Z[col*3+2]; }
        else { int c2 = col - NN; zc0 = Z3d[c2*3+0]; zc1 = Z3d[c2*3+1]; zc2 = Z3d[c2*3+2]; }
        float r0 = zr0-zc0, r1 = zr1-zc1, r2 = zr2-zc2;
        float d = sqrtf(r0*r0 + r1*r1 + r2*r2 + 1e-8f);
        sdist[t] = d;
        float inv = 1.0f / d;
        sunit[t*3+0] = r0*inv; sunit[t*3+1] = r1*inv; sunit[t*3+2] = r2*inv;
        float cl = fminf(d * (1.0f/CUTV), 1.0f);
        senvd[t] = 0.5f * (cosf(PI_F*cl) + 1.0f);
        float cl2 = fminf(fmaxf(dval * (1.0f/CUTV), 0.f), 1.0f);
        senv2[t] = 0.5f * (cosf(PI_F*cl2) + 1.0f);
    }
    __syncthreads();

    const float cstep = CUTV / 63.0f;
    const float i2w2  = 1.0f / (2.0f * (CUTV/64.0f) * (CUTV/64.0f));

    /* --- phase-A feats (fp32, types 0/2) --- */
    if (type == 0) {
        #pragma unroll
        for (int it = 0; it < 16; it++) {
            int idx = t + it*128; int e = idx & 31, k = idx >> 5;
            feats[e*FSL + k] = E2d_feat[(size_t)k*E1C + base + e];
        }
    } else if (type == 2) {
        #pragma unroll
        for (int it = 0; it < 16; it++) {
            int idx = t + it*128; int e = idx & 31, k = idx >> 5;
            float diff = sdval[e] - k*cstep;
            feats[e*FSL + k] = expf(-diff*diff*i2w2) * senv2[e];
        }
    }
    /* --- RBF(dist) directly to bf16 hi/lo cols 64..95 --- */
    #pragma unroll
    for (int it = 0; it < 8; it++) {
        int idx = t + it*128; int e = idx & 31, kp = idx >> 5;  /* kp 0..31 */
        float da = sdist[e] - (2*kp)*cstep;
        float db = sdist[e] - (2*kp+1)*cstep;
        float va = expf(-da*da*i2w2) * senvd[e];
        float vb = expf(-db*db*i2w2) * senvd[e];
        unsigned hi, lo;
        bfsplit2(va, vb, hi, lo);
        xshiw[e*100 + 64 + kp] = hi;
        xslow[e*100 + 64 + kp] = lo;
    }
    /* --- gather node projection + edge-type bias --- */
    u64t gn[4][4];
    #pragma unroll
    for (int j = 0; j < 4; j++) {
        const float* np = g_nproj + (size_t)scol[ebte + 4*j]*128;
        ulonglong2 ga = *(const ulonglong2*)(np + c0);
        ulonglong2 gb = *(const ulonglong2*)(np + c1);
        gn[0][j] = ga.x; gn[1][j] = ga.y; gn[2][j] = gb.x; gn[3][j] = gb.y;
    }
    u64t et2[4];
    {
        ulonglong2 ea = *(const ulonglong2*)(g_etb + type*128 + c0);
        ulonglong2 eb2 = *(const ulonglong2*)(g_etb + type*128 + c1);
        et2[0] = ea.x; et2[1] = ea.y; et2[2] = eb2.x; et2[3] = eb2.y;
    }
    __syncthreads();

    /* --- phase A: act = nproj[col]+etb (+feats@W^T); silu; bf16 to cols 0..63 --- */
    {
        u64t acc[4][4] = {};
        if (type == 0)
            gemm64s(g_Wc2dT, feats + ebte*FSL, c0, c1, acc);
        else if (type == 2)
            gemm64s(g_WcrbfT, feats + ebte*FSL, c0, c1, acc);
        #pragma unroll
        for (int j = 0; j < 4; j++) {
            int e = ebte + 4*j;
            float v[8];
            #pragma unroll
            for (int q = 0; q < 4; q++) {
                u64t s = fadd2(acc[q][j], fadd2(gn[q][j], et2[q]));
                float a = lo2(s), b = hi2(s);
                v[2*q]   = a / (1.0f + expf(-a));
                v[2*q+1] = b / (1.0f + expf(-b));
            }
            unsigned h0,l0,h1,l1,h2,l2,h3,l3;
            bfsplit2(v[0], v[1], h0, l0);
            bfsplit2(v[2], v[3], h1, l1);
            bfsplit2(v[4], v[5], h2, l2);
            bfsplit2(v[6], v[7], h3, l3);
            *(uint2*)&xshiw[e*100 + (c0>>1)] = make_uint2(h0, h1);
            *(uint2*)&xslow[e*100 + (c0>>1)] = make_uint2(l0, l1);
            *(uint2*)&xshiw[e*100 + (c1>>1)] = make_uint2(h2, h3);
            *(uint2*)&xslow[e*100 + (c1>>1)] = make_uint2(l2, l3);
        }
    }
    __syncthreads();

    /* --- phase C: kt-major bf16x3 tensor GEMM; qc order {1,0,2} --- */
    unsigned xshi_s = (unsigned)__cvta_generic_to_shared(xshiw);
    unsigned xslo_s = (unsigned)__cvta_generic_to_shared(xslow);
    unsigned a_off  = (unsigned)((l & 15)*400 + (l >> 4)*16);

    #pragma unroll 1
    for (int qi = 0; qi < 3; qi++) {
        int qc = (qi == 0) ? 1 : (qi == 1 ? 0 : 2);
        float accP[2][4][4], accW[2][4][4];
        #pragma unroll
        for (int mt = 0; mt < 2; mt++)
            #pragma unroll
            for (int nt = 0; nt < 4; nt++)
                #pragma unroll
                for (int r = 0; r < 4; r++) { accP[mt][nt][r] = 0.f; accW[mt][nt][r] = 0.f; }

        const uint4* WB = g_WfHL + l;
        int recb = (qc*12)*16 + (w << 2);

        #pragma unroll 2
        for (int kt = 0; kt < 8; kt++) {          /* accP: k 0..127 */
            unsigned ah0[4], ah1[4], al0[4], al1[4];
            ldmA(ah0, xshi_s + a_off + kt*32);
            ldmA(ah1, xshi_s + a_off + kt*32 + 6400);
            ldmA(al0, xslo_s + a_off + kt*32);
            ldmA(al1, xslo_s + a_off + kt*32 + 6400);
            #pragma unroll
            for (int nt = 0; nt < 4; nt++) {
                uint4 bv = WB[(size_t)(recb + kt*16 + nt)*32];
                mmabf(accP[0][nt], ah0, bv.x, bv.y);
                mmabf(accP[1][nt], ah1, bv.x, bv.y);
                mmabf(accP[0][nt], ah0, bv.z, bv.w);
                mmabf(accP[1][nt], ah1, bv.z, bv.w);
                mmabf(accP[0][nt], al0, bv.x, bv.y);
                mmabf(accP[1][nt], al1, bv.x, bv.y);
            }
        }
        #pragma unroll 2
        for (int kt = 8; kt < 12; kt++) {         /* accW: k 128..191 */
            unsigned ah0[4], ah1[4], al0[4], al1[4];
            ldmA(ah0, xshi_s + a_off + kt*32);
            ldmA(ah1, xshi_s + a_off + kt*32 + 6400);
            ldmA(al0, xslo_s + a_off + kt*32);
            ldmA(al1, xslo_s + a_off + kt*32 + 6400);
            #pragma unroll
            for (int nt = 0; nt < 4; nt++) {
                uint4 bv = WB[(size_t)(recb + kt*16 + nt)*32];
                mmabf(accW[0][nt], ah0, bv.x, bv.y);
                mmabf(accW[1][nt], ah1, bv.x, bv.y);
                mmabf(accW[0][nt], ah0, bv.z, bv.w);
                mmabf(accW[1][nt], ah1, bv.z, bv.w);
                mmabf(accW[0][nt], al0, bv.x, bv.y);
                mmabf(accW[1][nt], al1, bv.x, bv.y);
            }
        }

        /* qc2 epilogue writes rgbuf (aliases xshiw/xslow): wait for all warps'
           final MMAs to finish reading xshi/xslo */
        if (qc == 2) __syncthreads();

        /* epilogue */
        #pragma unroll
        for (int nt = 0; nt < 4; nt++) {
            int ch0 = (w << 5) + (nt << 3) + ((l & 3) << 1);
            float2 bp = *(const float2*)&b_phi2[qc*128 + ch0];
            float2 bm = *(const float2*)&b_msg [qc*128 + ch0];
            #pragma unroll
            for (int mt = 0; mt < 2; mt++) {
                float m0 = (accP[mt][nt][0] + bp.x) * (accW[mt][nt][0] + bm.x);
                float m1 = (accP[mt][nt][1] + bp.y) * (accW[mt][nt][1] + bm.y);
                float m2 = (accP[mt][nt][2] + bp.x) * (accW[mt][nt][2] + bm.x);
                float m3 = (accP[mt][nt][3] + bp.y) * (accW[mt][nt][3] + bm.y);
                int e1 = (mt << 4) + (l >> 2);
                int e2 = e1 + 8;
                if (qc == 1) {
                    *(float2*)(g_vg + (size_t)(base+e1)*128 + ch0) = make_float2(m0, m1);
                    *(float2*)(g_vg + (size_t)(base+e2)*128 + ch0) = make_float2(m2, m3);
                } else if (qc == 2) {
                    *(float2*)&rgbuf[e1*VGL + ch0] = make_float2(m0, m1);
                    *(float2*)&rgbuf[e2*VGL + ch0] = make_float2(m2, m3);
                } else { /* qc == 0 : H scatter (sector-optimal) */
                    red2(out + (size_t)srow[e1]*128 + ch0, m0, m1);
                    red2(out + (size_t)srow[e2]*128 + ch0, m2, m3);
                }
            }
        }
    }

    /* --- cooperative V pass: coalesced gather + red4 scatter --- */
    __syncthreads();
    {
        int e   = t >> 2;
        int seg = t & 3;
        int row = srow[e], col = scol[e];
        float u0 = sunit[e*3+0], u1 = sunit[e*3+1], u2 = sunit[e*3+2];
        int r0 = seg % 3;
        float ua = (r0==0) ? u0 : ((r0==1) ? u1 : u2);
        float ub = (r0==0) ? u1 : ((r0==1) ? u2 : u0);
        float uc = (r0==0) ? u2 : ((r0==1) ? u0 : u1);
        const float* vrow = V + (size_t)col*384;
        float* op = out + HN + (size_t)row*384;
        const float* vgr = g_vg + (size_t)(base+e)*128;
        const float* rgr = rgbuf + e*VGL;
        int ch = (seg == 3) ? 4 : seg;
        int r  = r0;
        #pragma unroll
        for (int i = 0; i < 24; i++) {
            int fo = 4*seg + 16*i;
            float4 vb;
            if (type != 1) vb = *(const float4*)(vrow + fo);
            else           vb = make_float4(0.f, 0.f, 0.f, 0.f);
            float vga = vgr[ch], vgb2 = vgr[ch+1];
            float rga = rgr[ch], rgb2 = rgr[ch+1];
            float uA, uB, uC;
            if (i % 3 == 0)      { uA = ua; uB = ub; uC = uc; }
            else if (i % 3 == 1) { uA = ub; uB = uc; uC = ua; }
            else                 { uA = uc; uB = ua; uC = ub; }
            bool cB = (r == 2);
            bool cC = (r >= 1);
            float vg1 = cB ? vgb2 : vga, rg1 = cB ? rgb2 : rga;
            float vg2 = cC ? vgb2 : vga, rg2 = cC ? rgb2 : rga;
            float dx = vb.x*vga + uA*rga;
            float dy = vb.y*vg1 + uB*rg1;
            float dz = vb.z*vg2 + uC*rg2;
            float dw = vb.w*vgb2 + uA*rgb2;
            red4(op + fo, dx, dy, dz, dw);
            ch += (r == 2) ? 6 : 5;
            r   = (r == 2) ? 0 : r + 1;
        }
    }
}

/* ---------------- finalize ---------------- */
__global__ void k_fin(float* __restrict__ out,
                      const unsigned char* __restrict__ m2d,
                      const unsigned char* __restrict__ m3d, int total)
{
    int idx = blockIdx.x*256 + threadIdx.x;
    if (idx >= total) return;
    int i = (idx < HN) ? (idx >> 7) : ((idx - HN) / 384);
    float v = out[idx];
    v = fminf(fmaxf(v, -100.f), 100.f);
    bool keep = ((m2d[i] | m3d[i] | g_mask[i]) != 0);
    out[idx] = keep ? v : 0.f;
}

#define SMEM_EDGE ((32*FSL + 3200 + 3200 + 2*32 + 4*32 + 96 + 32) * sizeof(float))

extern "C" void kernel_launch(void* const* d_in, const int* in_sizes, int n_in,
                              void* d_out, int out_size)
{
    int o = (in_sizes[3] == 1) ? 1 : 0;
    const float* H      = (const float*)d_in[0];
    const float* V      = (const float*)d_in[1];
    const float* Z      = (const float*)d_in[2];
    const float* H2d    = (const float*)d_in[3+o];
    const unsigned char* m2d = (const unsigned char*)d_in[4+o];
    const int*   E2didx = (const int*)d_in[5+o];
    const float* E2dfeat= (const float*)d_in[6+o];
    const float* Z3d    = (const float*)d_in[7+o];
    const unsigned char* m3d = (const unsigned char*)d_in[8+o];
    const int*   Edidx  = (const int*)d_in[9+o];
    const float* Edval  = (const float*)d_in[10+o];
    const float* virt   = (const float*)d_in[11+o];
    const float* ETe    = (const float*)d_in[12+o];
    const float* Wrbf   = (const float*)d_in[13+o];
    const float* We2d   = (const float*)d_in[14+o];
    const float* Wi     = (const float*)d_in[15+o];
    const float* Wphi1  = (const float*)d_in[16+o];
    const float* bphi1  = (const float*)d_in[17+o];
    const float* Wphi2  = (const float*)d_in[18+o];
    const float* bphi2  = (const float*)d_in[19+o];
    const float* Wmsg   = (const float*)d_in[20+o];
    const float* bmsg   = (const float*)d_in[21+o];
    float* out = (float*)d_out;

    cudaMemsetAsync(d_out, 0, (size_t)out_size * sizeof(float));
    k_pre<<<1121, 256>>>(Wi, Wphi1, bphi1, We2d, Wrbf, ETe, virt, Wphi2, Wmsg, Edidx);
    k_nproj<<<1250, 128>>>(H, H2d);
    cudaFuncSetAttribute(k_edge, cudaFuncAttributeMaxDynamicSharedMemorySize,
                         (int)SMEM_EDGE);
    k_edge<<<NBT, 128, SMEM_EDGE>>>(E2didx, E2dfeat, Edidx, Edval, Z, Z3d, V,
                                    bphi2, bmsg, out);
    k_fin<<<(HN + 3*HN + 255)/256, 256>>>(out, m2d, m3d, HN + 3*HN);
}